// round 4
// baseline (speedup 1.0000x reference)
#include <cuda_runtime.h>
#include <cuda_bf16.h>
#include <mma.h>
#include <math.h>

using namespace nvcuda;

// ---------------- problem constants ----------------
#define LYRS 12
#define NH   12
#define DMODEL 768
#define DHEAD 64
#define DMLP 3072
#define NVOCAB 50257
#define BATCH 2
#define SEQ 1024
#define MROWS (BATCH*SEQ)          // 2048

// ---------------- scratch (device globals; no allocation allowed) ----------------
__device__ float g_resid[MROWS*DMODEL];
__device__ float g_x[MROWS*DMODEL];
__device__ float g_q[MROWS*DMODEL];
__device__ float g_k[MROWS*DMODEL];
__device__ float g_v[MROWS*DMODEL];
__device__ float g_z[MROWS*DMODEL];
__device__ float g_h[MROWS*DMLP];

// ---------------- embedding ----------------
__global__ void embed_kernel(const int* __restrict__ tokens,
                             const float* __restrict__ WE,
                             const float* __restrict__ Wpos,
                             float* __restrict__ resid)
{
    int idx = blockIdx.x * blockDim.x + threadIdx.x;
    if (idx >= MROWS*DMODEL) return;
    int d  = idx % DMODEL;
    int bs = idx / DMODEL;
    int s  = bs % SEQ;
    int tok = tokens[bs];
    resid[idx] = WE[(long)tok*DMODEL + d] + Wpos[s*DMODEL + d];
}

// ---------------- layernorm (one block per row) ----------------
__global__ void layernorm_kernel(const float* __restrict__ in,
                                 const float* __restrict__ w,
                                 const float* __restrict__ b,
                                 float* __restrict__ out)
{
    __shared__ float sm[16];
    int row = blockIdx.x;
    const float* x = in + (long)row * DMODEL;
    int tid = threadIdx.x;          // 256 threads

    float s = 0.f, ss = 0.f;
    for (int i = tid; i < DMODEL; i += 256) {
        float v = x[i];
        s += v; ss += v*v;
    }
    #pragma unroll
    for (int o = 16; o > 0; o >>= 1) {
        s  += __shfl_xor_sync(0xffffffffu, s,  o);
        ss += __shfl_xor_sync(0xffffffffu, ss, o);
    }
    if ((tid & 31) == 0) { sm[tid >> 5] = s; sm[8 + (tid >> 5)] = ss; }
    __syncthreads();
    if (tid < 8) {
        float a = sm[tid], c = sm[8 + tid];
        #pragma unroll
        for (int o = 4; o > 0; o >>= 1) {
            a += __shfl_xor_sync(0xffu, a, o);
            c += __shfl_xor_sync(0xffu, c, o);
        }
        if (tid == 0) { sm[0] = a; sm[8] = c; }
    }
    __syncthreads();
    float mean = sm[0] * (1.f / DMODEL);
    float var  = sm[8] * (1.f / DMODEL) - mean * mean;
    float inv  = rsqrtf(var + 1e-5f);
    for (int i = tid; i < DMODEL; i += 256) {
        out[(long)row*DMODEL + i] = (x[i] - mean) * inv * w[i] + b[i];
    }
}

// ---------------- tf32 tensor-core GEMM ----------------
// Block tile 128x128, BK=16, 256 threads = 8 warps, warp tile 64x32.
// cp.async 2-stage pipeline. Epilogue staged through smem (aliased).
#define TBM 128
#define TBN 128
#define TBK 16
#define ALD 20      // A smem row stride (pad 4)
#define BLD 132     // B smem row stride (pad 4)
#define CLD 132
#define ASTAGE (TBM*ALD)   // 2560 floats
#define BSTAGE (TBK*BLD)   // 2112 floats
#define SMEM_FLOATS (TBM*CLD)   // 16896 floats = 67584 B (>= 2*ASTAGE+2*BSTAGE = 9344)
#define SMEM_BYTES (SMEM_FLOATS*4)

__device__ __forceinline__ void cpa16(float* dst, const float* src) {
    unsigned d = (unsigned)__cvta_generic_to_shared(dst);
    asm volatile("cp.async.ca.shared.global [%0], [%1], 16;\n" :: "r"(d), "l"(src));
}
__device__ __forceinline__ void cpa4(float* dst, const float* src, bool ok) {
    unsigned d = (unsigned)__cvta_generic_to_shared(dst);
    int sz = ok ? 4 : 0;
    asm volatile("cp.async.ca.shared.global [%0], [%1], 4, %2;\n" :: "r"(d), "l"(src), "r"(sz));
}
__device__ __forceinline__ void cpa_commit() {
    asm volatile("cp.async.commit_group;\n" ::);
}

typedef wmma::fragment<wmma::matrix_a, 16,16,8, wmma::precision::tf32, wmma::row_major> AFrag;
typedef wmma::fragment<wmma::matrix_b, 16,16,8, wmma::precision::tf32, wmma::row_major> BFrag;
typedef wmma::fragment<wmma::accumulator, 16,16,8, float> CFrag;

template<bool GELU, bool RES>
__device__ __forceinline__ void gemm_body(
    const float* __restrict__ A, const float* __restrict__ Bm,
    const float* __restrict__ bias, const float* __restrict__ res,
    float* __restrict__ C, int M, int N, int K,
    int headN, int strideH, int strideKB)
{
    extern __shared__ float smem[];
    float* As[2] = { smem,            smem + ASTAGE };
    float* Bs[2] = { smem + 2*ASTAGE, smem + 2*ASTAGE + BSTAGE };
    float* Cs    = smem;   // epilogue alias

    int tid = threadIdx.x;
    int wid = tid >> 5;
    int bm = blockIdx.y * TBM;
    int bn = blockIdx.x * TBN;

    // A load mapping: each thread 2x float4 (rows ar, ar+64; col ac)
    int ar = tid >> 2;
    int ac = (tid & 3) << 2;
    // B load mapping: row br (0..15), 8 consecutive cols from bc
    int br = tid >> 4;
    int bc = (tid & 15) << 3;

    int bbase[8]; bool bok[8];
    #pragma unroll
    for (int j = 0; j < 8; j++) {
        int n = bn + bc + j;
        bok[j] = (n < N);
        int nn = bok[j] ? n : 0;
        int h = nn / headN;
        int e = nn - h*headN;
        bbase[j] = h*strideH + e;
    }

    CFrag acc[4][2];
    #pragma unroll
    for (int i = 0; i < 4; i++)
        #pragma unroll
        for (int j = 0; j < 2; j++) wmma::fill_fragment(acc[i][j], 0.f);

    int wm = (wid >> 2) * 64;   // 0 or 64
    int wn = (wid & 3) * 32;    // 0..96

    const int nIters = K / TBK;

    // prologue: async load tile 0 into stage 0
    {
        const float* a0 = A + (long)(bm + ar)*K + ac;
        cpa16(As[0] + ar*ALD + ac, a0);
        cpa16(As[0] + (ar+64)*ALD + ac, a0 + (long)64*K);
        #pragma unroll
        for (int j = 0; j < 8; j++)
            cpa4(Bs[0] + br*BLD + bc + j, Bm + bbase[j] + (long)br*strideKB, bok[j]);
        cpa_commit();
    }

    for (int it = 0; it < nIters; it++) {
        int cur = it & 1;
        if (it + 1 < nIters) {
            int nxt = (it+1) & 1;
            int k0 = (it+1) * TBK;
            const float* a0 = A + (long)(bm + ar)*K + k0 + ac;
            cpa16(As[nxt] + ar*ALD + ac, a0);
            cpa16(As[nxt] + (ar+64)*ALD + ac, a0 + (long)64*K);
            #pragma unroll
            for (int j = 0; j < 8; j++)
                cpa4(Bs[nxt] + br*BLD + bc + j, Bm + bbase[j] + (long)(k0+br)*strideKB, bok[j]);
            cpa_commit();
            asm volatile("cp.async.wait_group 1;\n" ::);
        } else {
            asm volatile("cp.async.wait_group 0;\n" ::);
        }
        __syncthreads();

        const float* as = As[cur];
        const float* bs = Bs[cur];
        #pragma unroll
        for (int ks = 0; ks < 2; ks++) {
            AFrag af[4];
            BFrag bf[2];
            #pragma unroll
            for (int mi = 0; mi < 4; mi++) {
                wmma::load_matrix_sync(af[mi], as + (wm + mi*16)*ALD + ks*8, ALD);
                #pragma unroll
                for (int e = 0; e < af[mi].num_elements; e++)
                    af[mi].x[e] = wmma::__float_to_tf32(af[mi].x[e]);
            }
            #pragma unroll
            for (int ni = 0; ni < 2; ni++) {
                wmma::load_matrix_sync(bf[ni], bs + (ks*8)*BLD + wn + ni*16, BLD);
                #pragma unroll
                for (int e = 0; e < bf[ni].num_elements; e++)
                    bf[ni].x[e] = wmma::__float_to_tf32(bf[ni].x[e]);
            }
            #pragma unroll
            for (int mi = 0; mi < 4; mi++)
                #pragma unroll
                for (int ni = 0; ni < 2; ni++)
                    wmma::mma_sync(acc[mi][ni], af[mi], bf[ni], acc[mi][ni]);
        }
        __syncthreads();
    }

    // epilogue: stage C through smem, then guarded fused store
    #pragma unroll
    for (int mi = 0; mi < 4; mi++)
        #pragma unroll
        for (int ni = 0; ni < 2; ni++)
            wmma::store_matrix_sync(Cs + (wm + mi*16)*CLD + wn + ni*16,
                                    acc[mi][ni], CLD, wmma::mem_row_major);
    __syncthreads();

    for (int idx = tid; idx < TBM*TBN; idx += 256) {
        int r = idx >> 7;
        int c = idx & 127;
        int n = bn + c;
        if (n < N) {
            float v = Cs[r*CLD + c] + bias[n];
            if (RES) v += res[(long)(bm + r)*N + n];
            if (GELU) {
                float xx = v;
                float x3 = xx*xx*xx;
                v = 0.5f*xx*(1.f + tanhf(0.7978845608028654f*(xx + 0.044715f*x3)));
            }
            C[(long)(bm + r)*N + n] = v;
        }
    }
}

template<bool GELU, bool RES>
__global__ void __launch_bounds__(256, 2) gemm_tc(
    const float* __restrict__ A, const float* __restrict__ Bm,
    const float* __restrict__ bias, const float* __restrict__ res,
    float* __restrict__ C, int M, int N, int K,
    int headN, int strideH, int strideKB)
{
    gemm_body<GELU,RES>(A, Bm, bias, res, C, M, N, K, headN, strideH, strideKB);
}

// fused QKV: blockIdx.z selects which projection
__global__ void __launch_bounds__(256, 2) qkv_tc(
    const float* __restrict__ A,
    const float* __restrict__ Wq, const float* __restrict__ Wk, const float* __restrict__ Wv,
    const float* __restrict__ bq, const float* __restrict__ bk, const float* __restrict__ bv,
    float* __restrict__ q, float* __restrict__ k, float* __restrict__ v)
{
    const float* B; const float* bias; float* C;
    int z = blockIdx.z;
    if (z == 0)      { B = Wq; bias = bq; C = q; }
    else if (z == 1) { B = Wk; bias = bk; C = k; }
    else             { B = Wv; bias = bv; C = v; }
    gemm_body<false,false>(A, B, bias, nullptr, C,
                           MROWS, DMODEL, DMODEL, DHEAD, DMODEL*DHEAD, DHEAD);
}

// ---------------- fused causal attention: one block per (q, h, b) ----------------
__global__ void attention_kernel(const float* __restrict__ q,
                                 const float* __restrict__ k,
                                 const float* __restrict__ v,
                                 float* __restrict__ z)
{
    __shared__ float qs[DHEAD];
    __shared__ float p[SEQ];
    __shared__ float red[8];
    __shared__ float zacc[4][DHEAD];

    int qi = blockIdx.x;
    int h  = blockIdx.y;
    int b  = blockIdx.z;
    int tid = threadIdx.x;                 // 256 threads

    const float* qptr = q + ((long)(b*SEQ + qi)*NH + h) * DHEAD;
    if (tid < DHEAD) qs[tid] = qptr[tid];
    __syncthreads();

    float lmax = -1e30f;
    for (int t = tid; t <= qi; t += 256) {
        const float* kp = k + ((long)(b*SEQ + t)*NH + h) * DHEAD;
        float s = 0.f;
        #pragma unroll
        for (int e = 0; e < DHEAD; e++) s += qs[e] * kp[e];
        s *= 0.125f;
        p[t] = s;
        lmax = fmaxf(lmax, s);
    }
    #pragma unroll
    for (int o = 16; o > 0; o >>= 1) lmax = fmaxf(lmax, __shfl_xor_sync(0xffffffffu, lmax, o));
    if ((tid & 31) == 0) red[tid >> 5] = lmax;
    __syncthreads();
    if (tid < 8) {
        float a = red[tid];
        #pragma unroll
        for (int o = 4; o > 0; o >>= 1) a = fmaxf(a, __shfl_xor_sync(0xffu, a, o));
        if (tid == 0) red[0] = a;
    }
    __syncthreads();
    float gmax = red[0];
    __syncthreads();

    float lsum = 0.f;
    for (int t = tid; t <= qi; t += 256) {
        float e = __expf(p[t] - gmax);
        p[t] = e;
        lsum += e;
    }
    #pragma unroll
    for (int o = 16; o > 0; o >>= 1) lsum += __shfl_xor_sync(0xffffffffu, lsum, o);
    if ((tid & 31) == 0) red[tid >> 5] = lsum;
    __syncthreads();
    if (tid < 8) {
        float a = red[tid];
        #pragma unroll
        for (int o = 4; o > 0; o >>= 1) a += __shfl_xor_sync(0xffu, a, o);
        if (tid == 0) red[0] = a;
    }
    __syncthreads();
    float inv = 1.f / red[0];

    int e = tid & 63;
    int g = tid >> 6;
    float acc = 0.f;
    for (int t = g; t <= qi; t += 4) {
        acc += p[t] * v[((long)(b*SEQ + t)*NH + h) * DHEAD + e];
    }
    zacc[g][e] = acc;
    __syncthreads();
    if (g == 0) {
        float zv = (zacc[0][e] + zacc[1][e] + zacc[2][e] + zacc[3][e]) * inv;
        z[((long)(b*SEQ + qi)*NH + h) * DHEAD + e] = zv;
    }
}

// ---------------- host-side orchestration ----------------
static inline dim3 gemm_grid(int M, int N) {
    return dim3((N + TBN - 1) / TBN, M / TBM);
}

extern "C" void kernel_launch(void* const* d_in, const int* in_sizes, int n_in,
                              void* d_out, int out_size)
{
    const int*   tokens = (const int*)  d_in[0];
    const float* W_E    = (const float*)d_in[1];
    const float* W_pos  = (const float*)d_in[2];
    const float* ln1_w  = (const float*)d_in[3];
    const float* ln1_b  = (const float*)d_in[4];
    const float* W_Q    = (const float*)d_in[5];
    const float* b_Q    = (const float*)d_in[6];
    const float* W_K    = (const float*)d_in[7];
    const float* b_K    = (const float*)d_in[8];
    const float* W_V    = (const float*)d_in[9];
    const float* b_V    = (const float*)d_in[10];
    const float* W_O    = (const float*)d_in[11];
    const float* b_O    = (const float*)d_in[12];
    const float* ln2_w  = (const float*)d_in[13];
    const float* ln2_b  = (const float*)d_in[14];
    const float* W_in   = (const float*)d_in[15];
    const float* b_in   = (const float*)d_in[16];
    const float* W_out  = (const float*)d_in[17];
    const float* b_out  = (const float*)d_in[18];
    const float* lnf_w  = (const float*)d_in[19];
    const float* lnf_b  = (const float*)d_in[20];
    const float* W_U    = (const float*)d_in[21];
    const float* b_U    = (const float*)d_in[22];
    float* out = (float*)d_out;

    float *p_resid, *p_x, *p_q, *p_k, *p_v, *p_z, *p_h;
    cudaGetSymbolAddress((void**)&p_resid, g_resid);
    cudaGetSymbolAddress((void**)&p_x, g_x);
    cudaGetSymbolAddress((void**)&p_q, g_q);
    cudaGetSymbolAddress((void**)&p_k, g_k);
    cudaGetSymbolAddress((void**)&p_v, g_v);
    cudaGetSymbolAddress((void**)&p_z, g_z);
    cudaGetSymbolAddress((void**)&p_h, g_h);

    // opt in to 67.6KB dynamic smem (idempotent)
    cudaFuncSetAttribute((const void*)gemm_tc<false,false>, cudaFuncAttributeMaxDynamicSharedMemorySize, SMEM_BYTES);
    cudaFuncSetAttribute((const void*)gemm_tc<false,true>,  cudaFuncAttributeMaxDynamicSharedMemorySize, SMEM_BYTES);
    cudaFuncSetAttribute((const void*)gemm_tc<true,false>,  cudaFuncAttributeMaxDynamicSharedMemorySize, SMEM_BYTES);
    cudaFuncSetAttribute((const void*)qkv_tc,               cudaFuncAttributeMaxDynamicSharedMemorySize, SMEM_BYTES);

    embed_kernel<<<(MROWS*DMODEL + 255)/256, 256>>>(tokens, W_E, W_pos, p_resid);

    const long headW = (long)NH * DMODEL * DHEAD;
    const long mlpW  = (long)DMODEL * DMLP;

    for (int l = 0; l < LYRS; l++) {
        layernorm_kernel<<<MROWS, 256>>>(p_resid, ln1_w + l*DMODEL, ln1_b + l*DMODEL, p_x);

        dim3 qg = gemm_grid(MROWS, DMODEL); qg.z = 3;
        qkv_tc<<<qg, 256, SMEM_BYTES>>>(
            p_x,
            W_Q + l*headW, W_K + l*headW, W_V + l*headW,
            b_Q + l*NH*DHEAD, b_K + l*NH*DHEAD, b_V + l*NH*DHEAD,
            p_q, p_k, p_v);

        attention_kernel<<<dim3(SEQ, NH, BATCH), 256>>>(p_q, p_k, p_v, p_z);

        gemm_tc<false,true><<<gemm_grid(MROWS, DMODEL), 256, SMEM_BYTES>>>(
            p_z, W_O + l*headW, b_O + l*DMODEL, p_resid, p_resid,
            MROWS, DMODEL, DMODEL, DMODEL, 0, DMODEL);

        layernorm_kernel<<<MROWS, 256>>>(p_resid, ln2_w + l*DMODEL, ln2_b + l*DMODEL, p_x);

        gemm_tc<true,false><<<gemm_grid(MROWS, DMLP), 256, SMEM_BYTES>>>(
            p_x, W_in + l*mlpW, b_in + l*DMLP, nullptr, p_h,
            MROWS, DMLP, DMODEL, DMLP, 0, DMLP);

        gemm_tc<false,true><<<gemm_grid(MROWS, DMODEL), 256, SMEM_BYTES>>>(
            p_h, W_out + l*mlpW, b_out + l*DMODEL, p_resid, p_resid,
            MROWS, DMODEL, DMLP, DMODEL, 0, DMODEL);
    }

    layernorm_kernel<<<MROWS, 256>>>(p_resid, lnf_w, lnf_b, p_x);

    gemm_tc<false,false><<<gemm_grid(MROWS, NVOCAB), 256, SMEM_BYTES>>>(
        p_x, W_U, b_U, nullptr, out,
        MROWS, NVOCAB, DMODEL, NVOCAB, 0, NVOCAB);
}

// round 6
// speedup vs baseline: 3.7595x; 3.7595x over previous
#include <cuda_runtime.h>
#include <mma.h>
#include <math.h>

using namespace nvcuda;

#define LYRS 12
#define NH 12
#define DMODEL 768
#define DHEAD 64
#define DMLP 3072
#define NVOCAB 50257
#define NVPAD 50304
#define BATCH 2
#define SEQ 1024
#define MROWS 2048

// ---- scratch (device globals; no allocation allowed) ----
__device__ float g_resid[MROWS*DMODEL];
__device__ float g_x[MROWS*DMODEL];
__device__ float g_q[MROWS*DMODEL];
__device__ float g_k[MROWS*DMODEL];
__device__ float g_v[MROWS*DMODEL];
__device__ float g_z[MROWS*DMODEL];
__device__ float g_h[MROWS*DMLP];
// repacked K-major [N][K] tf32-rounded weights
__device__ float g_bq[LYRS*DMODEL*DMODEL];
__device__ float g_bk[LYRS*DMODEL*DMODEL];
__device__ float g_bv[LYRS*DMODEL*DMODEL];
__device__ float g_bo[LYRS*DMODEL*DMODEL];
__device__ float g_bin[LYRS*DMLP*DMODEL];
__device__ float g_bout[LYRS*DMODEL*DMLP];
__device__ float g_bu[(long)NVPAD*DMODEL];

__device__ __forceinline__ float to_tf32(float x) {
    unsigned u; asm("cvt.rna.tf32.f32 %0, %1;" : "=r"(u) : "f"(x));
    return __uint_as_float(u);
}
__device__ __forceinline__ void cpa16(float* dst, const float* src) {
    unsigned d = (unsigned)__cvta_generic_to_shared(dst);
    asm volatile("cp.async.cg.shared.global [%0], [%1], 16;" :: "r"(d), "l"(src));
}

// ---- embedding ----
__global__ void embed_kernel(const int* __restrict__ tokens, const float* __restrict__ WE,
                             const float* __restrict__ Wpos, float* __restrict__ resid)
{
    int idx = blockIdx.x * blockDim.x + threadIdx.x;
    if (idx >= MROWS*DMODEL) return;
    int d = idx % DMODEL, bs = idx / DMODEL, s = bs % SEQ;
    resid[idx] = WE[(long)tokens[bs]*DMODEL + d] + Wpos[s*DMODEL + d];
}

// ---- layernorm (rounds output to tf32) ----
__global__ void layernorm_kernel(const float* __restrict__ in, const float* __restrict__ w,
                                 const float* __restrict__ b, float* __restrict__ out)
{
    __shared__ float sm[16];
    int row = blockIdx.x, tid = threadIdx.x;
    const float* x = in + (long)row * DMODEL;
    float s = 0.f, ss = 0.f;
    for (int i = tid; i < DMODEL; i += 256) { float v = x[i]; s += v; ss += v*v; }
    #pragma unroll
    for (int o = 16; o > 0; o >>= 1) {
        s  += __shfl_xor_sync(0xffffffffu, s,  o);
        ss += __shfl_xor_sync(0xffffffffu, ss, o);
    }
    if ((tid & 31) == 0) { sm[tid>>5] = s; sm[8 + (tid>>5)] = ss; }
    __syncthreads();
    if (tid < 8) {
        float a = sm[tid], c = sm[8+tid];
        #pragma unroll
        for (int o = 4; o > 0; o >>= 1) {
            a += __shfl_xor_sync(0xffu, a, o);
            c += __shfl_xor_sync(0xffu, c, o);
        }
        if (tid == 0) { sm[0] = a; sm[8] = c; }
    }
    __syncthreads();
    float mean = sm[0] * (1.f/DMODEL);
    float var  = sm[8] * (1.f/DMODEL) - mean*mean;
    float inv  = rsqrtf(var + 1e-5f);
    for (int i = tid; i < DMODEL; i += 256)
        out[(long)row*DMODEL + i] = to_tf32((x[i]-mean)*inv*w[i] + b[i]);
}

// ---- weight repack: per-head [L][H][D][DH] -> [L][h*64+e][D] (tf32) ----
__global__ void trans_head(const float* __restrict__ src, float* __restrict__ dst)
{
    __shared__ float t[32][33];
    int tx = threadIdx.x, ty = threadIdx.y;
    int d0 = blockIdx.x*32, e0 = blockIdx.y*32, lh = blockIdx.z;
    int l = lh / NH, h = lh % NH;
    const float* sp = src + (long)lh*DMODEL*DHEAD;
    float* dp = dst + (long)l*DMODEL*DMODEL;
    #pragma unroll
    for (int i = 0; i < 4; i++)
        t[ty+8*i][tx] = sp[(long)(d0+ty+8*i)*DHEAD + e0+tx];
    __syncthreads();
    #pragma unroll
    for (int i = 0; i < 4; i++)
        dp[(long)(h*64 + e0+ty+8*i)*DMODEL + d0+tx] = to_tf32(t[tx][ty+8*i]);
}

// ---- weight repack: [K,N] -> [Npad,K] transpose (tf32, zero pad) ----
__global__ void trans_kn(const float* __restrict__ src, float* __restrict__ dst,
                         int K, int N, int Npad)
{
    __shared__ float t[32][33];
    int tx = threadIdx.x, ty = threadIdx.y;
    int n0 = blockIdx.x*32, k0 = blockIdx.y*32, l = blockIdx.z;
    const float* sp = src + (long)l*K*N;
    float* dp = dst + (long)l*Npad*K;
    #pragma unroll
    for (int i = 0; i < 4; i++) {
        int n = n0+tx;
        t[ty+8*i][tx] = (n < N) ? sp[(long)(k0+ty+8*i)*N + n] : 0.f;
    }
    __syncthreads();
    #pragma unroll
    for (int i = 0; i < 4; i++)
        dp[(long)(n0+ty+8*i)*K + k0+tx] = to_tf32(t[tx][ty+8*i]);
}

// ---- wmma tf32 GEMM: C[2048,nvalid] = A[2048,K] @ B[Npad,K]^T ----
// TM x 128 block tile, BK=16, 3-stage cp.async, 8 warps.
#define ALD 20
#define CLD 132

typedef wmma::fragment<wmma::matrix_a, 16,16,8, wmma::precision::tf32, wmma::row_major> AFrag;
typedef wmma::fragment<wmma::matrix_b, 16,16,8, wmma::precision::tf32, wmma::col_major> BFrag;
typedef wmma::fragment<wmma::accumulator, 16,16,8, float> CFrag;

template<int TM, bool GELU, bool RES>
__device__ __forceinline__ void gemm_core(
    const float* __restrict__ A, const float* __restrict__ B,
    const float* __restrict__ bias, const float* __restrict__ res,
    float* __restrict__ C, int K, int nvalid)
{
    extern __shared__ float smem[];
    const int STAGE = TM*ALD + 128*ALD;
    const int MI = TM/64;      // m-frags per warp: 2 (TM=128) or 1 (TM=64)... see below
    int tid = threadIdx.x, wid = tid >> 5;
    int bm = blockIdx.y * TM, bn = blockIdx.x * 128;

    // warp layout: 2 rows x 4 cols of warps
    int wm = (wid >> 2) * (TM/2);   // warp covers TM/2 rows => MI2 = TM/32 frags... 
    int wn = (wid & 3) * 32;
    const int MF = TM/32;           // m-frags per warp (4 for TM=128, 2 for TM=64)

    CFrag acc[TM/32][2];
    #pragma unroll
    for (int i = 0; i < MF; i++)
        #pragma unroll
        for (int j = 0; j < 2; j++) wmma::fill_fragment(acc[i][j], 0.f);

    const int nIter = K >> 4;

    // load mappings
    // A: TM*4 float4s; B: 512 float4s
    auto loadStage = [&](int sidx, int it) {
        float* as = smem + sidx*STAGE;
        float* bs = as + TM*ALD;
        const float* Ag = A + (long)bm*K + it*16;
        const float* Bg = B + (long)bn*K + it*16;
        #pragma unroll
        for (int i = 0; i < TM/64; i++) {
            int idx = tid + 256*i;
            int row = idx >> 2, k4 = (idx & 3) << 2;
            cpa16(as + row*ALD + k4, Ag + (long)row*K + k4);
        }
        #pragma unroll
        for (int i = 0; i < 2; i++) {
            int idx = tid + 256*i;
            int row = idx >> 2, k4 = (idx & 3) << 2;
            cpa16(bs + row*ALD + k4, Bg + (long)row*K + k4);
        }
        asm volatile("cp.async.commit_group;" ::);
    };

    loadStage(0, 0);
    if (nIter > 1) loadStage(1, 1); else asm volatile("cp.async.commit_group;" ::);

    for (int it = 0; it < nIter; it++) {
        int cur = it % 3;
        if (it + 2 < nIter) asm volatile("cp.async.wait_group 1;" ::);
        else                asm volatile("cp.async.wait_group 0;" ::);
        __syncthreads();
        if (it + 2 < nIter) loadStage((it+2) % 3, it+2);

        const float* as = smem + cur*STAGE;
        const float* bs = as + TM*ALD;
        #pragma unroll
        for (int ks = 0; ks < 2; ks++) {
            AFrag af[TM/32];
            BFrag bf[2];
            #pragma unroll
            for (int mi = 0; mi < MF; mi++)
                wmma::load_matrix_sync(af[mi], as + (wm + mi*16)*ALD + ks*8, ALD);
            #pragma unroll
            for (int ni = 0; ni < 2; ni++)
                wmma::load_matrix_sync(bf[ni], bs + (wn + ni*16)*ALD + ks*8, ALD);
            #pragma unroll
            for (int mi = 0; mi < MF; mi++)
                #pragma unroll
                for (int ni = 0; ni < 2; ni++)
                    wmma::mma_sync(acc[mi][ni], af[mi], bf[ni], acc[mi][ni]);
        }
        __syncthreads();
    }

    // epilogue via smem (alias stages)
    float* Cs = smem;
    #pragma unroll
    for (int mi = 0; mi < MF; mi++)
        #pragma unroll
        for (int ni = 0; ni < 2; ni++)
            wmma::store_matrix_sync(Cs + (wm + mi*16)*CLD + wn + ni*16,
                                    acc[mi][ni], CLD, wmma::mem_row_major);
    __syncthreads();

    for (int idx = tid; idx < TM*128; idx += 256) {
        int r = idx >> 7, c = idx & 127;
        int n = bn + c;
        if (n < nvalid) {
            float v = Cs[r*CLD + c] + bias[n];
            long gr = bm + r;
            if (RES) v += res[gr*nvalid + n];
            if (GELU) {
                float t3 = v*v*v;
                v = 0.5f*v*(1.f + tanhf(0.7978845608028654f*(v + 0.044715f*t3)));
                v = to_tf32(v);
            }
            C[gr*nvalid + n] = v;
        }
    }
}

template<int TM, bool GELU, bool RES>
__global__ void __launch_bounds__(256) gemm_w(
    const float* __restrict__ A, const float* __restrict__ B,
    const float* __restrict__ bias, const float* __restrict__ res,
    float* __restrict__ C, int K, int nvalid)
{
    gemm_core<TM,GELU,RES>(A, B, bias, res, C, K, nvalid);
}

__global__ void __launch_bounds__(256) qkv_w(
    const float* __restrict__ A,
    const float* __restrict__ Bq, const float* __restrict__ Bk, const float* __restrict__ Bv,
    const float* __restrict__ bq, const float* __restrict__ bk, const float* __restrict__ bv,
    float* __restrict__ q, float* __restrict__ k, float* __restrict__ v)
{
    const float* B; const float* bias; float* C;
    int z = blockIdx.z;
    if (z == 0)      { B = Bq; bias = bq; C = q; }
    else if (z == 1) { B = Bk; bias = bk; C = k; }
    else             { B = Bv; bias = bv; C = v; }
    gemm_core<128,false,false>(A, B, bias, nullptr, C, DMODEL, DMODEL);
}

// ---- flash attention: block per (64 q-rows, h, b); 64 threads, 1 row/thread ----
__global__ void __launch_bounds__(64) flash_kernel(
    const float* __restrict__ q, const float* __restrict__ k,
    const float* __restrict__ v, float* __restrict__ z)
{
    __shared__ float Qs[64][68];
    __shared__ float Ks[32][68];
    __shared__ float Vs[32][68];
    __shared__ float Ss[64][33];
    int tid = threadIdx.x;
    int qt = blockIdx.x, h = blockIdx.y, b = blockIdx.z;
    int qi = qt*64 + tid;
    long qrow = (long)(b*SEQ + qi)*DMODEL + h*DHEAD;

    for (int r = 0; r < 64; r++)
        Qs[r][tid] = q[(long)(b*SEQ + qt*64 + r)*DMODEL + h*DHEAD + tid];

    float o[64];
    #pragma unroll
    for (int e = 0; e < 64; e++) o[e] = 0.f;
    float m = -1e30f, l = 0.f;

    int ntiles = qt*2 + 2;
    for (int kt = 0; kt < ntiles; kt++) {
        __syncthreads();
        long kb = (long)(b*SEQ + kt*32)*DMODEL + h*DHEAD;
        for (int r = 0; r < 32; r++) {
            Ks[r][tid] = k[kb + (long)r*DMODEL + tid];
            Vs[r][tid] = v[kb + (long)r*DMODEL + tid];
        }
        __syncthreads();
        for (int jg = 0; jg < 4; jg++) {
            float sa[8];
            #pragma unroll
            for (int i = 0; i < 8; i++) sa[i] = 0.f;
            for (int e4 = 0; e4 < 16; e4++) {
                float4 qv = *(const float4*)&Qs[tid][e4*4];
                #pragma unroll
                for (int i = 0; i < 8; i++) {
                    float4 kk = *(const float4*)&Ks[jg*8 + i][e4*4];
                    sa[i] += qv.x*kk.x + qv.y*kk.y + qv.z*kk.z + qv.w*kk.w;
                }
            }
            #pragma unroll
            for (int i = 0; i < 8; i++) Ss[tid][jg*8 + i] = sa[i];
        }
        float tmax = -1e30f;
        for (int j = 0; j < 32; j++) {
            int kj = kt*32 + j;
            float sv = (kj <= qi) ? Ss[tid][j]*0.125f : -1e30f;
            Ss[tid][j] = sv;
            tmax = fmaxf(tmax, sv);
        }
        float mn = fmaxf(m, tmax);
        float sc = __expf(m - mn);
        float ts = 0.f;
        for (int j = 0; j < 32; j++) {
            float p = __expf(Ss[tid][j] - mn);
            Ss[tid][j] = p;
            ts += p;
        }
        l = l*sc + ts;
        m = mn;
        #pragma unroll
        for (int e = 0; e < 64; e++) o[e] *= sc;
        for (int j = 0; j < 32; j++) {
            float p = Ss[tid][j];
            #pragma unroll
            for (int e4 = 0; e4 < 16; e4++) {
                float4 vv = *(const float4*)&Vs[j][e4*4];
                o[e4*4+0] += p*vv.x; o[e4*4+1] += p*vv.y;
                o[e4*4+2] += p*vv.z; o[e4*4+3] += p*vv.w;
            }
        }
    }
    float inv = 1.f / l;
    #pragma unroll
    for (int e = 0; e < 64; e++) z[qrow + e] = to_tf32(o[e]*inv);
}

// smem sizes (bytes)
#define SM128 (128*CLD*4)          // 67584 (>= 3*STAGE128 = 61440)
#define SM64  (3*(64*ALD+128*ALD)*4 > 64*CLD*4 ? 3*(64*ALD+128*ALD)*4 : 64*CLD*4)

extern "C" void kernel_launch(void* const* d_in, const int* in_sizes, int n_in,
                              void* d_out, int out_size)
{
    const int*   tokens = (const int*)  d_in[0];
    const float* W_E    = (const float*)d_in[1];
    const float* W_pos  = (const float*)d_in[2];
    const float* ln1_w  = (const float*)d_in[3];
    const float* ln1_b  = (const float*)d_in[4];
    const float* W_Q    = (const float*)d_in[5];
    const float* b_Q    = (const float*)d_in[6];
    const float* W_K    = (const float*)d_in[7];
    const float* b_K    = (const float*)d_in[8];
    const float* W_V    = (const float*)d_in[9];
    const float* b_V    = (const float*)d_in[10];
    const float* W_O    = (const float*)d_in[11];
    const float* b_O    = (const float*)d_in[12];
    const float* ln2_w  = (const float*)d_in[13];
    const float* ln2_b  = (const float*)d_in[14];
    const float* W_in   = (const float*)d_in[15];
    const float* b_in   = (const float*)d_in[16];
    const float* W_out  = (const float*)d_in[17];
    const float* b_out  = (const float*)d_in[18];
    const float* lnf_w  = (const float*)d_in[19];
    const float* lnf_b  = (const float*)d_in[20];
    const float* W_U    = (const float*)d_in[21];
    const float* b_U    = (const float*)d_in[22];
    float* out = (float*)d_out;

    float *p_resid, *p_x, *p_q, *p_k, *p_v, *p_z, *p_h;
    float *p_bq, *p_bk, *p_bv, *p_bo, *p_bin, *p_bout, *p_bu;
    cudaGetSymbolAddress((void**)&p_resid, g_resid);
    cudaGetSymbolAddress((void**)&p_x, g_x);
    cudaGetSymbolAddress((void**)&p_q, g_q);
    cudaGetSymbolAddress((void**)&p_k, g_k);
    cudaGetSymbolAddress((void**)&p_v, g_v);
    cudaGetSymbolAddress((void**)&p_z, g_z);
    cudaGetSymbolAddress((void**)&p_h, g_h);
    cudaGetSymbolAddress((void**)&p_bq, g_bq);
    cudaGetSymbolAddress((void**)&p_bk, g_bk);
    cudaGetSymbolAddress((void**)&p_bv, g_bv);
    cudaGetSymbolAddress((void**)&p_bo, g_bo);
    cudaGetSymbolAddress((void**)&p_bin, g_bin);
    cudaGetSymbolAddress((void**)&p_bout, g_bout);
    cudaGetSymbolAddress((void**)&p_bu, g_bu);

    cudaFuncSetAttribute((const void*)gemm_w<128,false,false>, cudaFuncAttributeMaxDynamicSharedMemorySize, SM128);
    cudaFuncSetAttribute((const void*)gemm_w<128,true,false>,  cudaFuncAttributeMaxDynamicSharedMemorySize, SM128);
    cudaFuncSetAttribute((const void*)gemm_w<64,false,true>,   cudaFuncAttributeMaxDynamicSharedMemorySize, SM64);
    cudaFuncSetAttribute((const void*)qkv_w,                   cudaFuncAttributeMaxDynamicSharedMemorySize, SM128);

    dim3 tb(32, 8);
    trans_head<<<dim3(24, 2, LYRS*NH), tb>>>(W_Q, p_bq);
    trans_head<<<dim3(24, 2, LYRS*NH), tb>>>(W_K, p_bk);
    trans_head<<<dim3(24, 2, LYRS*NH), tb>>>(W_V, p_bv);
    trans_kn<<<dim3(24, 24, LYRS), tb>>>(W_O, p_bo, DMODEL, DMODEL, DMODEL);
    trans_kn<<<dim3(96, 24, LYRS), tb>>>(W_in, p_bin, DMODEL, DMLP, DMLP);
    trans_kn<<<dim3(24, 96, LYRS), tb>>>(W_out, p_bout, DMLP, DMODEL, DMODEL);
    trans_kn<<<dim3(NVPAD/32, 24, 1), tb>>>(W_U, p_bu, DMODEL, NVOCAB, NVPAD);

    embed_kernel<<<(MROWS*DMODEL + 255)/256, 256>>>(tokens, W_E, W_pos, p_resid);

    for (int l = 0; l < LYRS; l++) {
        layernorm_kernel<<<MROWS, 256>>>(p_resid, ln1_w + l*DMODEL, ln1_b + l*DMODEL, p_x);

        qkv_w<<<dim3(6, 16, 3), 256, SM128>>>(
            p_x,
            p_bq + (long)l*DMODEL*DMODEL, p_bk + (long)l*DMODEL*DMODEL, p_bv + (long)l*DMODEL*DMODEL,
            b_Q + l*DMODEL, b_K + l*DMODEL, b_V + l*DMODEL,
            p_q, p_k, p_v);

        flash_kernel<<<dim3(SEQ/64, NH, BATCH), 64>>>(p_q, p_k, p_v, p_z);

        gemm_w<64,false,true><<<dim3(6, 32), 256, SM64>>>(
            p_z, p_bo + (long)l*DMODEL*DMODEL, b_O + l*DMODEL, p_resid, p_resid,
            DMODEL, DMODEL);

        layernorm_kernel<<<MROWS, 256>>>(p_resid, ln2_w + l*DMODEL, ln2_b + l*DMODEL, p_x);

        gemm_w<128,true,false><<<dim3(24, 16), 256, SM128>>>(
            p_x, p_bin + (long)l*DMLP*DMODEL, b_in + l*DMLP, nullptr, p_h,
            DMODEL, DMLP);

        gemm_w<64,false,true><<<dim3(6, 32), 256, SM64>>>(
            p_h, p_bout + (long)l*DMODEL*DMLP, b_out + l*DMODEL, p_resid, p_resid,
            DMLP, DMODEL);
    }

    layernorm_kernel<<<MROWS, 256>>>(p_resid, lnf_w, lnf_b, p_x);

    gemm_w<128,false,false><<<dim3(NVPAD/128, 16), 256, SM128>>>(
        p_x, p_bu, b_U, nullptr, out, DMODEL, NVOCAB);
}